// round 4
// baseline (speedup 1.0000x reference)
#include <cuda_runtime.h>
#include <cstdint>

#define D_MODEL 512
#define NH 8
#define HDIM 64
#define NS 8
#define KN 64
#define BN 2048
#define NQ 64  // NS*NH flattened (qi = s*8 + h)

// ---------------- persistent device scratch (no allocations allowed) ----------------
__device__ float g_Q[NS * D_MODEL];          // Q = shift @ Wq^T + bq   [s][j]
__device__ float g_qb[NQ];                   // Q[s,h,:] . bk[h]        [qi]
__device__ float g_QKT[D_MODEL * NQ];        // QK folded vec, d-major  [d][qi]
__device__ float g_WvT[D_MODEL * D_MODEL];   // Wv transposed           [d][j]
__device__ float g_WoT[D_MODEL * D_MODEL];   // Wo transposed           [d][e]

// ---------------- precompute kernels (tiny, run every launch) ----------------
__global__ void pre_q(const float* __restrict__ shift, const float* __restrict__ Wq,
                      const float* __restrict__ bq) {
    int s = blockIdx.x, j = threadIdx.x;
    const float* sr = shift + s * D_MODEL;
    const float* wr = Wq + j * D_MODEL;
    float acc = 0.f;
    for (int d = 0; d < D_MODEL; d++) acc += sr[d] * wr[d];
    g_Q[s * D_MODEL + j] = acc + bq[j];
}

__global__ void pre_qk(const float* __restrict__ Wk, const float* __restrict__ bk) {
    int qi = blockIdx.x, d = threadIdx.x;
    int s = qi >> 3, h = qi & 7;
    const float* qrow = g_Q + s * D_MODEL + h * HDIM;
    float acc = 0.f;
    for (int hd = 0; hd < HDIM; hd++) acc += qrow[hd] * Wk[(h * HDIM + hd) * D_MODEL + d];
    g_QKT[d * NQ + qi] = acc;
    if (d == 0) {
        float qb = 0.f;
        for (int hd = 0; hd < HDIM; hd++) qb += qrow[hd] * bk[h * HDIM + hd];
        g_qb[qi] = qb;
    }
}

__global__ void pre_t(const float* __restrict__ Wv, const float* __restrict__ Wo) {
    int r = blockIdx.x, d = threadIdx.x;
    g_WvT[d * D_MODEL + r] = Wv[r * D_MODEL + d];
    g_WoT[d * D_MODEL + r] = Wo[r * D_MODEL + d];
}

// ---------------- main fused kernel: one block per batch ----------------
struct SmemLayout {
    float encT[D_MODEL][68];   // enc transposed [d][k], pad 68 (conflict-free, 16B rows)
    float attn[NQ][68];        // logits -> softmax probs [qi][k]
    float A[NQ][132];          // A chunk: [qi][dc<128], pad 132
    float ctx[NS][D_MODEL];    // context [s][j]
    float dist[KN];
    float red[8][NS][2];       // per-warp LN partials
    float mu[NS];
    float rstd[NS];
    unsigned char validb[KN];
};

__global__ __launch_bounds__(256, 1)
void attn_main(const float* __restrict__ enc, const int* __restrict__ valid,
               const float* __restrict__ dist, const float* __restrict__ shift,
               const float* __restrict__ bv, const float* __restrict__ bo,
               const float* __restrict__ lnw, const float* __restrict__ lnb,
               const float* __restrict__ cosp, float* __restrict__ out) {
    extern __shared__ char smem_raw[];
    SmemLayout& sm = *reinterpret_cast<SmemLayout*>(smem_raw);
    const int t = threadIdx.x;
    const int b = blockIdx.x;

    // ---- P0: stage enc[b] transposed into smem ----
    const float4* encb = reinterpret_cast<const float4*>(enc + (size_t)b * KN * D_MODEL);
    #pragma unroll
    for (int it = 0; it < 32; it++) {
        int idx = t + it * 256;           // 8192 float4 total
        float4 v = encb[idx];
        int k = idx >> 7;                 // idx*4 / 512
        int d = (idx & 127) << 2;
        sm.encT[d][k] = v.x; sm.encT[d + 1][k] = v.y;
        sm.encT[d + 2][k] = v.z; sm.encT[d + 3][k] = v.w;
    }
    if (t < KN) {
        sm.dist[t] = dist[b * KN + t];
        sm.validb[t] = (valid[b * KN + t] != 0) ? 1 : 0;   // ret_valid is int32
    }
    __syncthreads();
    const int anyv = __syncthreads_or((t < KN) ? (int)sm.validb[t] : 0);
    const float cs = cosp[0];

    // ---- P1: logits[qi][k] = scale*(enc.QK + qb) + dist*cos, masked ----
    {
        const int qi = t >> 2, kg = t & 3;
        float acc[16];
        #pragma unroll
        for (int i = 0; i < 16; i++) acc[i] = 0.f;
        #pragma unroll 4
        for (int d = 0; d < D_MODEL; d++) {
            float qv = g_QKT[d * NQ + qi];
            const float4* er = reinterpret_cast<const float4*>(&sm.encT[d][kg * 16]);
            #pragma unroll
            for (int m = 0; m < 4; m++) {
                float4 e4 = er[m];
                acc[m * 4 + 0] += qv * e4.x; acc[m * 4 + 1] += qv * e4.y;
                acc[m * 4 + 2] += qv * e4.z; acc[m * 4 + 3] += qv * e4.w;
            }
        }
        float qbv = g_qb[qi];
        #pragma unroll
        for (int i = 0; i < 16; i++) {
            int k = kg * 16 + i;
            float lg = (acc[i] + qbv) * 0.125f + sm.dist[k] * cs;
            if (!sm.validb[k]) lg = -10000.0f;
            sm.attn[qi][k] = lg;
        }
    }
    __syncthreads();

    // ---- P2: softmax per (h,s) row ----
    if (t < NQ) {
        float mx = -1e30f;
        for (int k = 0; k < KN; k++) mx = fmaxf(mx, sm.attn[t][k]);
        float sum = 0.f;
        for (int k = 0; k < KN; k++) {
            float e = expf(sm.attn[t][k] - mx);
            sm.attn[t][k] = e;
            sum += e;
        }
        float inv = 1.0f / sum;
        for (int k = 0; k < KN; k++) sm.attn[t][k] *= inv;
    }
    __syncthreads();

    // ---- P3: A = attn @ enc (chunked over d), ctx += A @ WvT ----
    float cacc[16];
    #pragma unroll
    for (int i = 0; i < 16; i++) cacc[i] = 0.f;
    const int j0 = t * 2;          // ctx/out column pair
    const int h = t >> 5;          // head for ctx phase (j0/64)
    const int qi2 = t & 63, dcg = t >> 6;

    for (int c = 0; c < 4; c++) {
        const int dbase = c * 128 + dcg * 32;
        float accA[32];
        #pragma unroll
        for (int j = 0; j < 32; j++) accA[j] = 0.f;
        #pragma unroll 4
        for (int k4 = 0; k4 < 16; k4++) {
            float4 a4 = *reinterpret_cast<const float4*>(&sm.attn[qi2][k4 * 4]);
            #pragma unroll
            for (int j = 0; j < 32; j++) {
                float4 e4 = *reinterpret_cast<const float4*>(&sm.encT[dbase + j][k4 * 4]);
                accA[j] += a4.x * e4.x + a4.y * e4.y + a4.z * e4.z + a4.w * e4.w;
            }
        }
        #pragma unroll
        for (int m = 0; m < 8; m++) {
            *reinterpret_cast<float4*>(&sm.A[qi2][dcg * 32 + m * 4]) =
                make_float4(accA[m * 4], accA[m * 4 + 1], accA[m * 4 + 2], accA[m * 4 + 3]);
        }
        __syncthreads();
        // ctx accumulate: thread owns columns {j0, j0+1} for all 8 s
        #pragma unroll 4
        for (int dc = 0; dc < 128; dc += 2) {
            int d = c * 128 + dc;
            float2 wv0 = *reinterpret_cast<const float2*>(&g_WvT[d * D_MODEL + j0]);
            float2 wv1 = *reinterpret_cast<const float2*>(&g_WvT[(d + 1) * D_MODEL + j0]);
            #pragma unroll
            for (int s8 = 0; s8 < 8; s8++) {
                float2 a2 = *reinterpret_cast<const float2*>(&sm.A[s8 * 8 + h][dc]);
                cacc[s8 * 2 + 0] += a2.x * wv0.x + a2.y * wv1.x;
                cacc[s8 * 2 + 1] += a2.x * wv0.y + a2.y * wv1.y;
            }
        }
        __syncthreads();
    }

    // ctx += bv (softmax rows sum to 1), stage in smem
    {
        float2 bvv = *reinterpret_cast<const float2*>(&bv[j0]);
        #pragma unroll
        for (int s8 = 0; s8 < 8; s8++) {
            sm.ctx[s8][j0]     = cacc[s8 * 2]     + bvv.x;
            sm.ctx[s8][j0 + 1] = cacc[s8 * 2 + 1] + bvv.y;
        }
    }
    __syncthreads();

    // ---- P4: out = ctx @ WoT + bo + shift, then LayerNorm ----
    float xv[16];
    #pragma unroll
    for (int i = 0; i < 16; i++) xv[i] = 0.f;
    #pragma unroll 4
    for (int d = 0; d < D_MODEL; d += 2) {
        float2 wo0 = *reinterpret_cast<const float2*>(&g_WoT[d * D_MODEL + j0]);
        float2 wo1 = *reinterpret_cast<const float2*>(&g_WoT[(d + 1) * D_MODEL + j0]);
        #pragma unroll
        for (int s8 = 0; s8 < 8; s8++) {
            float2 c2 = *reinterpret_cast<const float2*>(&sm.ctx[s8][d]);
            xv[s8 * 2]     += c2.x * wo0.x + c2.y * wo1.x;
            xv[s8 * 2 + 1] += c2.x * wo0.y + c2.y * wo1.y;
        }
    }
    float2 bov = *reinterpret_cast<const float2*>(&bo[j0]);
    float p[8], q[8];
    #pragma unroll
    for (int s8 = 0; s8 < 8; s8++) {
        float2 sh = *reinterpret_cast<const float2*>(&shift[s8 * D_MODEL + j0]);
        xv[s8 * 2]     += bov.x + sh.x;
        xv[s8 * 2 + 1] += bov.y + sh.y;
        p[s8] = xv[s8 * 2] + xv[s8 * 2 + 1];
        q[s8] = xv[s8 * 2] * xv[s8 * 2] + xv[s8 * 2 + 1] * xv[s8 * 2 + 1];
    }
    #pragma unroll
    for (int s8 = 0; s8 < 8; s8++) {
        #pragma unroll
        for (int off = 16; off; off >>= 1) {
            p[s8] += __shfl_xor_sync(0xffffffffu, p[s8], off);
            q[s8] += __shfl_xor_sync(0xffffffffu, q[s8], off);
        }
    }
    const int w = t >> 5, lane = t & 31;
    if (lane == 0) {
        #pragma unroll
        for (int s8 = 0; s8 < 8; s8++) {
            sm.red[w][s8][0] = p[s8];
            sm.red[w][s8][1] = q[s8];
        }
    }
    __syncthreads();
    if (t < NS) {
        float S = 0.f, Q2 = 0.f;
        #pragma unroll
        for (int w2 = 0; w2 < 8; w2++) { S += sm.red[w2][t][0]; Q2 += sm.red[w2][t][1]; }
        float m = S * (1.0f / D_MODEL);
        float var = Q2 * (1.0f / D_MODEL) - m * m;
        sm.mu[t] = m;
        sm.rstd[t] = rsqrtf(var + 1e-5f);
    }
    __syncthreads();
    const float av = anyv ? 1.0f : 0.0f;
    float2 lw = *reinterpret_cast<const float2*>(&lnw[j0]);
    float2 lb = *reinterpret_cast<const float2*>(&lnb[j0]);
    float* ob = out + (size_t)b * NS * D_MODEL;
    #pragma unroll
    for (int s8 = 0; s8 < 8; s8++) {
        float m = sm.mu[s8], rs = sm.rstd[s8];
        float y0 = ((xv[s8 * 2]     - m) * rs * lw.x + lb.x) * av;
        float y1 = ((xv[s8 * 2 + 1] - m) * rs * lw.y + lb.y) * av;
        *reinterpret_cast<float2*>(&ob[s8 * D_MODEL + j0]) = make_float2(y0, y1);
    }
}

// ---------------- launch ----------------
extern "C" void kernel_launch(void* const* d_in, const int* in_sizes, int n_in,
                              void* d_out, int out_size) {
    const float*   enc   = (const float*)d_in[0];
    const int*     valid = (const int*)d_in[1];     // jax bool -> int32 in harness
    const float*   dist  = (const float*)d_in[2];
    const float*   shift = (const float*)d_in[3];
    const float*   Wq    = (const float*)d_in[4];
    const float*   bq    = (const float*)d_in[5];
    const float*   Wk    = (const float*)d_in[6];
    const float*   bk    = (const float*)d_in[7];
    const float*   Wv    = (const float*)d_in[8];
    const float*   bv    = (const float*)d_in[9];
    const float*   Wo    = (const float*)d_in[10];
    const float*   bo    = (const float*)d_in[11];
    const float*   lnw   = (const float*)d_in[12];
    const float*   lnb   = (const float*)d_in[13];
    const float*   cosp  = (const float*)d_in[14];
    float* out = (float*)d_out;

    pre_q<<<NS, D_MODEL>>>(shift, Wq, bq);
    pre_qk<<<NQ, D_MODEL>>>(Wk, bk);
    pre_t<<<D_MODEL, D_MODEL>>>(Wv, Wo);

    int smem = (int)sizeof(SmemLayout);
    cudaFuncSetAttribute(attn_main, cudaFuncAttributeMaxDynamicSharedMemorySize, smem);
    attn_main<<<BN, 256, smem>>>(enc, valid, dist, shift, bv, bo, lnw, lnb, cosp, out);
}

// round 5
// speedup vs baseline: 1.7406x; 1.7406x over previous
#include <cuda_runtime.h>
#include <cstdint>

#define DM 512
#define NSH 8
#define KN 64
#define BN 2048
#define NQ 64   // NSH*NH flattened: qi = s*8 + h

typedef unsigned long long ull;
__device__ __forceinline__ ull pk2(float lo, float hi) {
    ull r; asm("mov.b64 %0,{%1,%2};" : "=l"(r) : "f"(lo), "f"(hi)); return r;
}
__device__ __forceinline__ void fma2(ull& a, ull x, ull y) {
    asm("fma.rn.f32x2 %0,%1,%2,%0;" : "+l"(a) : "l"(x), "l"(y));
}
__device__ __forceinline__ float2 up2(ull v) {
    float2 f; asm("mov.b64 {%0,%1},%2;" : "=f"(f.x), "=f"(f.y) : "l"(v)); return f;
}

// ---------------- persistent device scratch ----------------
__device__ float g_Q[NSH * DM];                 // shift @ Wq^T + bq
__device__ float g_qb[NQ];                      // Q[s,h,:] . bk[h]
__device__ float g_QKT[DM * NQ];                // folded QK vec, d-major [d][qi]
__device__ float g_A[(size_t)BN * NQ * DM];     // A = attn @ enc   (268 MB)
__device__ float g_ctx[(size_t)BN * NSH * DM];  // ctx              (33.5 MB)
__device__ int   g_anyv[BN];

// ---------------- precompute kernels ----------------
__global__ void pre_q(const float* __restrict__ shift, const float* __restrict__ Wq,
                      const float* __restrict__ bq) {
    int s = blockIdx.x, j = threadIdx.x;
    const float* sr = shift + s * DM;
    const float* wr = Wq + j * DM;
    float acc = 0.f;
    for (int d = 0; d < DM; d++) acc += sr[d] * wr[d];
    g_Q[s * DM + j] = acc + bq[j];
}

__global__ void pre_qk(const float* __restrict__ Wk, const float* __restrict__ bk) {
    int qi = blockIdx.x, d = threadIdx.x;
    int s = qi >> 3, h = qi & 7;
    const float* qrow = g_Q + s * DM + h * 64;
    float acc = 0.f;
    for (int hd = 0; hd < 64; hd++) acc += qrow[hd] * Wk[(h * 64 + hd) * DM + d];
    g_QKT[d * NQ + qi] = acc;
    if (d == 0) {
        float qb = 0.f;
        for (int hd = 0; hd < 64; hd++) qb += qrow[hd] * bk[h * 64 + hd];
        g_qb[qi] = qb;
    }
}

// ---------------- kernel A: logits + softmax + A = attn@enc ----------------
struct SmA {
    float enc[64 * 512];     // [k][d], 16B-block XOR swizzle on d by ((k>>2)&7)<<2
    float qk[64][68];        // staged QKT chunk [dlocal][qi]
    float attn[64][68];      // logits [qi][k]
    float attnT[64][68];     // softmax probs, k-major [k][qi]
    float dist[64];
    int   valid[64];
};

__global__ __launch_bounds__(256, 1)
void kA(const float* __restrict__ enc, const int* __restrict__ valid,
        const float* __restrict__ dist, const float* __restrict__ cosp) {
    extern __shared__ char raw[];
    SmA& sm = *reinterpret_cast<SmA*>(raw);
    const int t = threadIdx.x, b = blockIdx.x;

    // P0: stage enc[b] (natural [k][d], swizzled 16B blocks)
    const float4* eb = reinterpret_cast<const float4*>(enc + (size_t)b * KN * DM);
    #pragma unroll
    for (int i = 0; i < 32; i++) {
        int idx = t + i * 256;
        float4 v = eb[idx];
        int k = idx >> 7;
        int d = (idx & 127) << 2;
        int off = d ^ (((k >> 2) & 7) << 2);
        *reinterpret_cast<float4*>(&sm.enc[k * 512 + off]) = v;
    }
    if (t < 64) { sm.dist[t] = dist[b * 64 + t]; sm.valid[t] = valid[b * 64 + t]; }
    int anyv = __syncthreads_or((t < 64) ? sm.valid[t] : 0);
    if (t == 0) g_anyv[b] = anyv;
    const float cs = cosp[0];

    // P1: logits[qi][k]; thread tile 4k x 4q
    {
        const int kg = t & 15, qg = t >> 4;
        const int k0 = kg * 4, q0 = qg * 4;
        const int sw = (kg & 7) << 2;
        ull a01[4], a23[4];
        #pragma unroll
        for (int i = 0; i < 4; i++) { a01[i] = 0ull; a23[i] = 0ull; }
        for (int db = 0; db < 512; db += 64) {
            __syncthreads();
            #pragma unroll
            for (int i = 0; i < 4; i++) {
                int lin = t + i * 256;
                int dl = lin >> 4, qq = (lin & 15) << 2;
                *reinterpret_cast<float4*>(&sm.qk[dl][qq]) =
                    *reinterpret_cast<const float4*>(&g_QKT[(db + dl) * 64 + qq]);
            }
            __syncthreads();
            #pragma unroll 4
            for (int dq = 0; dq < 64; dq += 4) {
                int dof = (db + dq) ^ sw;
                float4 e0 = *reinterpret_cast<const float4*>(&sm.enc[(k0 + 0) * 512 + dof]);
                float4 e1 = *reinterpret_cast<const float4*>(&sm.enc[(k0 + 1) * 512 + dof]);
                float4 e2 = *reinterpret_cast<const float4*>(&sm.enc[(k0 + 2) * 512 + dof]);
                float4 e3 = *reinterpret_cast<const float4*>(&sm.enc[(k0 + 3) * 512 + dof]);
                ulonglong2 qv0 = *reinterpret_cast<const ulonglong2*>(&sm.qk[dq + 0][q0]);
                ulonglong2 qv1 = *reinterpret_cast<const ulonglong2*>(&sm.qk[dq + 1][q0]);
                ulonglong2 qv2 = *reinterpret_cast<const ulonglong2*>(&sm.qk[dq + 2][q0]);
                ulonglong2 qv3 = *reinterpret_cast<const ulonglong2*>(&sm.qk[dq + 3][q0]);
                float ev[4][4] = {{e0.x, e0.y, e0.z, e0.w}, {e1.x, e1.y, e1.z, e1.w},
                                  {e2.x, e2.y, e2.z, e2.w}, {e3.x, e3.y, e3.z, e3.w}};
                ulonglong2 qv[4] = {qv0, qv1, qv2, qv3};
                #pragma unroll
                for (int dd = 0; dd < 4; dd++) {
                    #pragma unroll
                    for (int kk = 0; kk < 4; kk++) {
                        ull ebc = pk2(ev[kk][dd], ev[kk][dd]);
                        fma2(a01[kk], ebc, qv[dd].x);
                        fma2(a23[kk], ebc, qv[dd].y);
                    }
                }
            }
        }
        float4 qbv = *reinterpret_cast<const float4*>(&g_qb[q0]);
        #pragma unroll
        for (int kk = 0; kk < 4; kk++) {
            int k = k0 + kk;
            float dv = sm.dist[k] * cs;
            bool ok = (sm.valid[k] != 0);
            float2 v01 = up2(a01[kk]), v23 = up2(a23[kk]);
            sm.attn[q0 + 0][k] = ok ? (v01.x + qbv.x) * 0.125f + dv : -10000.f;
            sm.attn[q0 + 1][k] = ok ? (v01.y + qbv.y) * 0.125f + dv : -10000.f;
            sm.attn[q0 + 2][k] = ok ? (v23.x + qbv.z) * 0.125f + dv : -10000.f;
            sm.attn[q0 + 3][k] = ok ? (v23.y + qbv.w) * 0.125f + dv : -10000.f;
        }
    }
    __syncthreads();

    // P2: softmax per qi row -> attnT[k][qi]
    if (t < 64) {
        float mx = -1e30f;
        for (int k = 0; k < 64; k++) mx = fmaxf(mx, sm.attn[t][k]);
        float sum = 0.f;
        for (int k = 0; k < 64; k++) {
            float e = expf(sm.attn[t][k] - mx);
            sm.attnT[k][t] = e;
            sum += e;
        }
        float inv = 1.0f / sum;
        for (int k = 0; k < 64; k++) sm.attnT[k][t] *= inv;
    }
    __syncthreads();

    // P3: A[qi][d] = sum_k attnT[k][qi] * enc[k][d]; thread tile 4q x (4d x 4 spread)
    {
        const int dg = t & 15, qg = t >> 4;
        const int q0 = qg * 4;
        #pragma unroll 1
        for (int half = 0; half < 2; half++) {
            const int dh = half * 256;
            ull acc[4][4][2];
            #pragma unroll
            for (int q = 0; q < 4; q++)
                #pragma unroll
                for (int i = 0; i < 4; i++) { acc[q][i][0] = 0ull; acc[q][i][1] = 0ull; }
            for (int k = 0; k < 64; k++) {
                float4 a4 = *reinterpret_cast<const float4*>(&sm.attnT[k][q0]);
                ull aq0 = pk2(a4.x, a4.x), aq1 = pk2(a4.y, a4.y);
                ull aq2 = pk2(a4.z, a4.z), aq3 = pk2(a4.w, a4.w);
                int rb = k * 512;
                int sw = ((k >> 2) & 7) << 2;
                #pragma unroll
                for (int i = 0; i < 4; i++) {
                    int dof = (dh + dg * 4 + i * 64) ^ sw;
                    ulonglong2 ev = *reinterpret_cast<const ulonglong2*>(&sm.enc[rb + dof]);
                    fma2(acc[0][i][0], aq0, ev.x); fma2(acc[0][i][1], aq0, ev.y);
                    fma2(acc[1][i][0], aq1, ev.x); fma2(acc[1][i][1], aq1, ev.y);
                    fma2(acc[2][i][0], aq2, ev.x); fma2(acc[2][i][1], aq2, ev.y);
                    fma2(acc[3][i][0], aq3, ev.x); fma2(acc[3][i][1], aq3, ev.y);
                }
            }
            #pragma unroll
            for (int q = 0; q < 4; q++) {
                float* Ar = g_A + ((size_t)b * 64 + q0 + q) * 512;
                #pragma unroll
                for (int i = 0; i < 4; i++) {
                    float2 lo = up2(acc[q][i][0]), hi = up2(acc[q][i][1]);
                    *reinterpret_cast<float4*>(&Ar[dh + dg * 4 + i * 64]) =
                        make_float4(lo.x, lo.y, hi.x, hi.y);
                }
            }
        }
    }
}

// ---------------- kernel B1: ctx = A @ Wv^T + bv (per head, tiled GEMM) ----------------
__global__ __launch_bounds__(256)
void kB1(const float* __restrict__ Wv, const float* __restrict__ bv) {
    __shared__ float AsT[32][132];   // [k][row], k-major
    __shared__ float Bs[32][68];     // [k][j]
    const int t = threadIdx.x;
    const int rt = blockIdx.x, h = blockIdx.y;
    const int rg = t >> 4, jg = t & 15;
    const int r0 = rg * 8, j0 = jg * 4;
    ull acc[8][2];
    #pragma unroll
    for (int i = 0; i < 8; i++) { acc[i][0] = 0ull; acc[i][1] = 0ull; }

    const int rA = t >> 1, khA = (t & 1) * 16;
    const size_t arow = ((size_t)(rt * 128 + rA) * 8 + h) * 512 + khA;
    const int jB = t >> 2, khB = (t & 3) * 8;
    const size_t brow = ((size_t)(h * 64 + jB)) * 512 + khB;

    for (int kb = 0; kb < 512; kb += 32) {
        __syncthreads();
        #pragma unroll
        for (int u = 0; u < 4; u++) {
            float4 v = *reinterpret_cast<const float4*>(&g_A[arow + kb + u * 4]);
            AsT[khA + u * 4 + 0][rA] = v.x; AsT[khA + u * 4 + 1][rA] = v.y;
            AsT[khA + u * 4 + 2][rA] = v.z; AsT[khA + u * 4 + 3][rA] = v.w;
        }
        #pragma unroll
        for (int u = 0; u < 2; u++) {
            float4 v = *reinterpret_cast<const float4*>(&Wv[brow + kb + u * 4]);
            Bs[khB + u * 4 + 0][jB] = v.x; Bs[khB + u * 4 + 1][jB] = v.y;
            Bs[khB + u * 4 + 2][jB] = v.z; Bs[khB + u * 4 + 3][jB] = v.w;
        }
        __syncthreads();
        #pragma unroll 8
        for (int kl = 0; kl < 32; kl++) {
            float4 aA = *reinterpret_cast<const float4*>(&AsT[kl][r0]);
            float4 aB = *reinterpret_cast<const float4*>(&AsT[kl][r0 + 4]);
            ulonglong2 bb = *reinterpret_cast<const ulonglong2*>(&Bs[kl][j0]);
            float av[8] = {aA.x, aA.y, aA.z, aA.w, aB.x, aB.y, aB.z, aB.w};
            #pragma unroll
            for (int rr = 0; rr < 8; rr++) {
                ull ap = pk2(av[rr], av[rr]);
                fma2(acc[rr][0], ap, bb.x);
                fma2(acc[rr][1], ap, bb.y);
            }
        }
    }
    float4 bvv = *reinterpret_cast<const float4*>(&bv[h * 64 + j0]);
    #pragma unroll
    for (int rr = 0; rr < 8; rr++) {
        float2 lo = up2(acc[rr][0]), hi = up2(acc[rr][1]);
        float4 o = make_float4(lo.x + bvv.x, lo.y + bvv.y, hi.x + bvv.z, hi.y + bvv.w);
        *reinterpret_cast<float4*>(&g_ctx[((size_t)(rt * 128 + r0 + rr)) * 512 + h * 64 + j0]) = o;
    }
}

// ---------------- kernel B2: x = ctx @ Wo^T + bo + shift, LayerNorm, mask ----------------
__global__ __launch_bounds__(256)
void kB2(const float* __restrict__ Wo, const float* __restrict__ bo,
         const float* __restrict__ shift, const float* __restrict__ lnw,
         const float* __restrict__ lnb, float* __restrict__ out) {
    __shared__ float Bs[16][516];    // [k][e]
    __shared__ float AsT[16][20];    // [k][row]
    __shared__ float red[8][8][2];
    __shared__ float muS[16], rsS[16];
    const int t = threadIdx.x;
    const int row0 = blockIdx.x * 16;
    const int rg = t >> 7, eg = t & 127;
    const int r0 = rg * 8, e0 = eg * 4;
    ull acc[8][2];
    #pragma unroll
    for (int i = 0; i < 8; i++) { acc[i][0] = 0ull; acc[i][1] = 0ull; }

    const int eS = t * 2;
    const int rA = t >> 4, klA = t & 15;

    for (int kb = 0; kb < 512; kb += 16) {
        __syncthreads();
        #pragma unroll
        for (int ee = 0; ee < 2; ee++) {
            int e = eS + ee;
            #pragma unroll
            for (int u = 0; u < 4; u++) {
                float4 v = *reinterpret_cast<const float4*>(&Wo[(size_t)e * 512 + kb + u * 4]);
                Bs[u * 4 + 0][e] = v.x; Bs[u * 4 + 1][e] = v.y;
                Bs[u * 4 + 2][e] = v.z; Bs[u * 4 + 3][e] = v.w;
            }
        }
        AsT[klA][rA] = g_ctx[((size_t)(row0 + rA)) * 512 + kb + klA];
        __syncthreads();
        #pragma unroll 4
        for (int kl = 0; kl < 16; kl++) {
            float4 aA = *reinterpret_cast<const float4*>(&AsT[kl][r0]);
            float4 aB = *reinterpret_cast<const float4*>(&AsT[kl][r0 + 4]);
            ulonglong2 ev = *reinterpret_cast<const ulonglong2*>(&Bs[kl][e0]);
            float av[8] = {aA.x, aA.y, aA.z, aA.w, aB.x, aB.y, aB.z, aB.w};
            #pragma unroll
            for (int rr = 0; rr < 8; rr++) {
                ull ap = pk2(av[rr], av[rr]);
                fma2(acc[rr][0], ap, ev.x);
                fma2(acc[rr][1], ap, ev.y);
            }
        }
    }

    // epilogue: + bo + shift, LayerNorm over 512 cols per row, any_valid mask
    const int w = t >> 5, lane = t & 31;
    float x[8][4], p[8], q[8];
    float4 bov = *reinterpret_cast<const float4*>(&bo[e0]);
    float4 lwv = *reinterpret_cast<const float4*>(&lnw[e0]);
    float4 lbv = *reinterpret_cast<const float4*>(&lnb[e0]);
    #pragma unroll
    for (int rr = 0; rr < 8; rr++) {
        int row = row0 + r0 + rr;
        int s = row & 7;
        float4 sh = *reinterpret_cast<const float4*>(&shift[s * 512 + e0]);
        float2 lo = up2(acc[rr][0]), hi = up2(acc[rr][1]);
        x[rr][0] = lo.x + bov.x + sh.x;
        x[rr][1] = lo.y + bov.y + sh.y;
        x[rr][2] = hi.x + bov.z + sh.z;
        x[rr][3] = hi.y + bov.w + sh.w;
        p[rr] = x[rr][0] + x[rr][1] + x[rr][2] + x[rr][3];
        q[rr] = x[rr][0] * x[rr][0] + x[rr][1] * x[rr][1]
              + x[rr][2] * x[rr][2] + x[rr][3] * x[rr][3];
    }
    #pragma unroll
    for (int rr = 0; rr < 8; rr++) {
        #pragma unroll
        for (int off = 16; off; off >>= 1) {
            p[rr] += __shfl_xor_sync(0xffffffffu, p[rr], off);
            q[rr] += __shfl_xor_sync(0xffffffffu, q[rr], off);
        }
    }
    if (lane == 0) {
        #pragma unroll
        for (int rr = 0; rr < 8; rr++) { red[w][rr][0] = p[rr]; red[w][rr][1] = q[rr]; }
    }
    __syncthreads();
    if (t < 16) {
        int rgs = t >> 3, rr = t & 7;
        float S = 0.f, Q2 = 0.f;
        #pragma unroll
        for (int w2 = 0; w2 < 4; w2++) {
            S += red[rgs * 4 + w2][rr][0];
            Q2 += red[rgs * 4 + w2][rr][1];
        }
        float m = S * (1.0f / 512.0f);
        float var = Q2 * (1.0f / 512.0f) - m * m;
        muS[t] = m;
        rsS[t] = rsqrtf(var + 1e-5f);
    }
    __syncthreads();
    #pragma unroll
    for (int rr = 0; rr < 8; rr++) {
        int row = row0 + r0 + rr;
        float av = g_anyv[row >> 3] ? 1.0f : 0.0f;
        float m = muS[r0 + rr], rs = rsS[r0 + rr];
        float4 o;
        o.x = ((x[rr][0] - m) * rs * lwv.x + lbv.x) * av;
        o.y = ((x[rr][1] - m) * rs * lwv.y + lbv.y) * av;
        o.z = ((x[rr][2] - m) * rs * lwv.z + lbv.z) * av;
        o.w = ((x[rr][3] - m) * rs * lwv.w + lbv.w) * av;
        *reinterpret_cast<float4*>(&out[(size_t)row * 512 + e0]) = o;
    }
}

// ---------------- launch ----------------
extern "C" void kernel_launch(void* const* d_in, const int* in_sizes, int n_in,
                              void* d_out, int out_size) {
    const float* enc   = (const float*)d_in[0];
    const int*   valid = (const int*)d_in[1];
    const float* dist  = (const float*)d_in[2];
    const float* shift = (const float*)d_in[3];
    const float* Wq    = (const float*)d_in[4];
    const float* bq    = (const float*)d_in[5];
    const float* Wk    = (const float*)d_in[6];
    const float* bk    = (const float*)d_in[7];
    const float* Wv    = (const float*)d_in[8];
    const float* bv    = (const float*)d_in[9];
    const float* Wo    = (const float*)d_in[10];
    const float* bo    = (const float*)d_in[11];
    const float* lnw   = (const float*)d_in[12];
    const float* lnb   = (const float*)d_in[13];
    const float* cosp  = (const float*)d_in[14];
    float* out = (float*)d_out;

    pre_q<<<NSH, DM>>>(shift, Wq, bq);
    pre_qk<<<NQ, DM>>>(Wk, bk);

    int smemA = (int)sizeof(SmA);
    cudaFuncSetAttribute(kA, cudaFuncAttributeMaxDynamicSharedMemorySize, smemA);
    kA<<<BN, 256, smemA>>>(enc, valid, dist, cosp);

    dim3 gB1(128, 8);
    kB1<<<gB1, 256>>>(Wv, bv);

    kB2<<<1024, 256>>>(Wo, bo, shift, lnw, lnb, out);
}